// round 2
// baseline (speedup 1.0000x reference)
#include <cuda_runtime.h>
#include <math.h>

#define D 768
#define B 64
#define P 12
#define F 32
#define R 44            // P + F leaf vectors per batch
#define M_TOT (B * R)   // 2816 rows

// Scratch for transformed leaf vectors Y[b][r][D]
__device__ float g_Y[(size_t)M_TOT * D];

// ---------------------------------------------------------------------------
// Kernel A: Y[m, n] = sum_k X[m,k] * W[n,k] + hb[n]
// X row m -> batch b = m/R, slot r = m%R  (r<P: package, else function r-P)
// BM=128, BN=64, BK=16, 256 threads, each thread 8x4 outputs.
// ---------------------------------------------------------------------------
#define BM 128
#define BN 64
#define BK 16

__global__ __launch_bounds__(256, 2)
void gemm_xwT(const float* __restrict__ pkg, const float* __restrict__ fun,
              const float* __restrict__ W, const float* __restrict__ hb) {
    __shared__ float As[BK][132];   // [k][m], padded (mult of 4 for f4 reads)
    __shared__ float Bs[BK][68];    // [k][n], padded

    const int m0  = blockIdx.y * BM;
    const int n0  = blockIdx.x * BN;
    const int tid = threadIdx.x;
    const int tx  = tid & 15;   // n direction (4 cols each)
    const int ty  = tid >> 4;   // m direction (8 rows each)

    float c[8][4];
    #pragma unroll
    for (int j = 0; j < 8; j++)
        #pragma unroll
        for (int l = 0; l < 4; l++) c[j][l] = 0.f;

    // Per-thread A-load source rows (2 float4 loads per k-step)
    const float* arow[2];
    int ak4[2];
    #pragma unroll
    for (int it = 0; it < 2; it++) {
        int idx = tid + it * 256;       // 0..511
        int ml  = idx >> 2;             // 0..127
        ak4[it] = idx & 3;
        int row = m0 + ml;
        int b   = row / R;
        int r   = row % R;
        arow[it] = (r < P) ? (pkg + ((size_t)b * P + r) * D)
                           : (fun + ((size_t)b * F + (r - P)) * D);
    }
    const int bn  = tid >> 2;           // 0..63
    const int bk4 = tid & 3;
    const float* brow = W + (size_t)(n0 + bn) * D;

    for (int k0 = 0; k0 < D; k0 += BK) {
        #pragma unroll
        for (int it = 0; it < 2; it++) {
            int idx = tid + it * 256;
            int ml  = idx >> 2;
            float4 v = *(const float4*)(arow[it] + k0 + ak4[it] * 4);
            As[ak4[it]*4 + 0][ml] = v.x;
            As[ak4[it]*4 + 1][ml] = v.y;
            As[ak4[it]*4 + 2][ml] = v.z;
            As[ak4[it]*4 + 3][ml] = v.w;
        }
        {
            float4 v = *(const float4*)(brow + k0 + bk4 * 4);
            Bs[bk4*4 + 0][bn] = v.x;
            Bs[bk4*4 + 1][bn] = v.y;
            Bs[bk4*4 + 2][bn] = v.z;
            Bs[bk4*4 + 3][bn] = v.w;
        }
        __syncthreads();
        #pragma unroll
        for (int k = 0; k < BK; k++) {
            float a[8], bb[4];
            #pragma unroll
            for (int j = 0; j < 8; j++) a[j] = As[k][ty * 8 + j];
            #pragma unroll
            for (int l = 0; l < 4; l++) bb[l] = Bs[k][tx * 4 + l];
            #pragma unroll
            for (int j = 0; j < 8; j++)
                #pragma unroll
                for (int l = 0; l < 4; l++)
                    c[j][l] += a[j] * bb[l];
        }
        __syncthreads();
    }

    const int col = n0 + tx * 4;
    float4 hb4 = *(const float4*)(hb + col);
    #pragma unroll
    for (int j = 0; j < 8; j++) {
        int row = m0 + ty * 8 + j;
        float4 o;
        o.x = c[j][0] + hb4.x;
        o.y = c[j][1] + hb4.y;
        o.z = c[j][2] + hb4.z;
        o.w = c[j][3] + hb4.w;
        *(float4*)(g_Y + (size_t)row * D + col) = o;
    }
}

// ---------------------------------------------------------------------------
// Kernel B: per-batch tree evaluation + fusion. grid=B, block=256.
// ---------------------------------------------------------------------------
__device__ __forceinline__ float warp_sum(float v) {
    #pragma unroll
    for (int o = 16; o > 0; o >>= 1) v += __shfl_xor_sync(0xffffffffu, v, o);
    return v;
}

// han over n vectors (smem pointers in ptrs): att_j = tanh(v_j) . q ;
// softmax over j ; out[k] = sum_j score_j * v_j[k]. Block-collective.
__device__ void block_han(float* const* ptrs, int n, const float* q,
                          float* att, float* out,
                          int tid, int lane, int wid, int nwarp, int NT) {
    for (int j = wid; j < n; j += nwarp) {
        const float* v = ptrs[j];
        float s = 0.f;
        for (int k = lane; k < D; k += 32) s += tanhf(v[k]) * q[k];
        s = warp_sum(s);
        if (lane == 0) att[j] = s;
    }
    __syncthreads();
    if (tid == 0) {
        float mx = -1e30f;
        for (int j = 0; j < n; j++) mx = fmaxf(mx, att[j]);
        float ssum = 0.f;
        for (int j = 0; j < n; j++) { float e = expf(att[j] - mx); att[j] = e; ssum += e; }
        float inv = 1.f / ssum;
        for (int j = 0; j < n; j++) att[j] *= inv;
    }
    __syncthreads();
    for (int k = tid; k < D; k += NT) {
        float acc = 0.f;
        for (int j = 0; j < n; j++) acc += att[j] * ptrs[j][k];
        out[k] = acc;   // safe in-place: each thread reads its own k before writing
    }
    __syncthreads();
}

__global__ void tree_kernel(const float* __restrict__ nl,
                            const int* __restrict__ levels,
                            const float* __restrict__ fu_w,
                            const float* __restrict__ fu_b,
                            float* __restrict__ out) {
    extern __shared__ float sm[];
    float* q      = sm;                      // D
    float* Ys     = sm + D;                  // R*D
    float* tmp    = Ys + (size_t)R * D;      // D
    float* rootv  = tmp + D;                 // D
    float* att    = rootv + D;               // 64
    int*   parent = (int*)(att + 64);        // 32
    int*   nchild = parent + 32;             // 32
    int*   ncur   = nchild + 32;             // 1 (+1 pad keeps 8B alignment)
    float** ptrs  = (float**)(ncur + 2);     // 44 pointers

    const int b    = blockIdx.x;
    const int tid  = threadIdx.x;
    const int lane = tid & 31;
    const int wid  = tid >> 5;
    const int NT   = blockDim.x;
    const int nwarp = NT >> 5;

    // Load query (nl_vec row) and all 44 transformed vectors to smem
    for (int k = tid; k < D; k += NT) q[k] = nl[(size_t)b * D + k];
    {
        const float4* src = (const float4*)(g_Y + (size_t)b * R * D);
        float4* dst = (float4*)Ys;
        for (int k = tid; k < (R * D) / 4; k += NT) dst[k] = src[k];
    }

    // Parse levels -> parent[] (-2 skipped, -1 root child, else function idx)
    if (tid == 0) {
        for (int i = 0; i < F; i++) { parent[i] = -2; nchild[i] = 0; }
        int curNode = -1, curLevel = -1;
        for (int i = 0; i < F; i++) {
            int l = levels[b * F + i];
            if (l == -1) break;
            if (l - curLevel == 1)      { parent[i] = curNode; curNode = i; curLevel = l; }
            else if (l == curLevel)     { parent[i] = parent[curNode]; curNode = i; }
            else if (l < curLevel) {
                int p = parent[curNode];
                for (int t = 0; t < curLevel - l; t++) p = parent[p];
                parent[i] = p; curNode = i; curLevel = l;
            }
            // else (jump >= +2): node skipped, state unchanged
        }
        for (int i = 0; i < F; i++) if (parent[i] >= 0) nchild[parent[i]]++;
    }
    __syncthreads();

    // Post-order: children have strictly larger indices -> descending sweep
    for (int i = F - 1; i >= 0; i--) {
        if (parent[i] == -2 || nchild[i] == 0) continue;
        if (tid == 0) {
            int n = 0;
            for (int j = i + 1; j < F; j++)
                if (parent[j] == i) ptrs[n++] = Ys + (size_t)(P + j) * D;
            *ncur = n;
        }
        __syncthreads();
        block_han(ptrs, *ncur, q, att, tmp, tid, lane, wid, nwarp, NT);
        if (tid == 0) { ptrs[0] = Ys + (size_t)(P + i) * D; ptrs[1] = tmp; }
        __syncthreads();
        block_han(ptrs, 2, q, att, Ys + (size_t)(P + i) * D, tid, lane, wid, nwarp, NT);
    }

    // Root: packages first, then level-0 functions, in index order
    if (tid == 0) {
        int n = 0;
        for (int r = 0; r < P; r++) ptrs[n++] = Ys + (size_t)r * D;
        for (int i = 0; i < F; i++)
            if (parent[i] == -1) ptrs[n++] = Ys + (size_t)(P + i) * D;
        *ncur = n;
    }
    __syncthreads();
    block_han(ptrs, *ncur, q, att, rootv, tid, lane, wid, nwarp, NT);

    // Fusion: a = softmax([nl.fu_w+b, ctx.fu_w+b]); out = a0*nl + a1*ctx
    if (wid < 2) {
        const float* v = (wid == 0) ? q : rootv;
        float s = 0.f;
        for (int k = lane; k < D; k += 32) s += v[k] * fu_w[k];
        s = warp_sum(s);
        if (lane == 0) att[wid] = s + fu_b[0];
    }
    __syncthreads();
    if (tid == 0) {
        float mx = fmaxf(att[0], att[1]);
        float e0 = expf(att[0] - mx), e1 = expf(att[1] - mx);
        float inv = 1.f / (e0 + e1);
        att[0] = e0 * inv; att[1] = e1 * inv;
    }
    __syncthreads();
    for (int k = tid; k < D; k += NT)
        out[(size_t)b * D + k] = att[0] * q[k] + att[1] * rootv[k];
}

// ---------------------------------------------------------------------------
// Launch
// ---------------------------------------------------------------------------
extern "C" void kernel_launch(void* const* d_in, const int* in_sizes, int n_in,
                              void* d_out, int out_size) {
    const float* nl  = (const float*)d_in[0];   // nl_vec        [64,768]
    const float* pkg = (const float*)d_in[1];   // package_embs  [64,12,768]
    const float* fun = (const float*)d_in[2];   // function_embs [64,32,768]
    const int*   lev = (const int*)  d_in[3];   // levels        [64,32]
    const float* hw  = (const float*)d_in[4];   // han_w [768,768]
    const float* hb  = (const float*)d_in[5];   // han_b [768]
    const float* fuw = (const float*)d_in[6];   // fu_w [1,768]
    const float* fub = (const float*)d_in[7];   // fu_b [1]
    float* out = (float*)d_out;                 // [64,768]

    dim3 g1(D / BN, M_TOT / BM);   // 12 x 22
    gemm_xwT<<<g1, 256>>>(pkg, fun, hw, hb);

    // shared: (D + R*D + D + D + 64) floats + 66 ints + 44 ptrs
    size_t smem = (size_t)(D + (size_t)R * D + D + D + 64) * sizeof(float)
                + 66 * sizeof(int) + 44 * sizeof(float*);
    cudaFuncSetAttribute(tree_kernel, cudaFuncAttributeMaxDynamicSharedMemorySize,
                         (int)smem);
    tree_kernel<<<B, 256, smem>>>(nl, lev, fuw, fub, out);
}

// round 3
// speedup vs baseline: 1.0060x; 1.0060x over previous
#include <cuda_runtime.h>
#include <math.h>

#define D 768
#define B 64
#define P 12
#define F 32
#define R 44            // P + F leaf vectors per batch
#define M_TOT (B * R)   // 2816 rows

// Scratch for transformed leaf vectors Y[b][r][D]
__device__ float g_Y[(size_t)M_TOT * D];

// ---------------------------------------------------------------------------
// Kernel A: Y[m, n] = sum_k X[m,k] * W[n,k] + hb[n]
// X row m -> batch b = m/R, slot r = m%R  (r<P: package, else function r-P)
// BM=128, BN=64, BK=16, 256 threads, each thread 8x4 outputs.
// ---------------------------------------------------------------------------
#define BM 128
#define BN 64
#define BK 16

__global__ __launch_bounds__(256, 2)
void gemm_xwT(const float* __restrict__ pkg, const float* __restrict__ fun,
              const float* __restrict__ W, const float* __restrict__ hb) {
    __shared__ float As[BK][132];   // [k][m], padded (mult of 4 for f4 reads)
    __shared__ float Bs[BK][68];    // [k][n], padded

    const int m0  = blockIdx.y * BM;
    const int n0  = blockIdx.x * BN;
    const int tid = threadIdx.x;
    const int tx  = tid & 15;   // n direction (4 cols each)
    const int ty  = tid >> 4;   // m direction (8 rows each)

    float c[8][4];
    #pragma unroll
    for (int j = 0; j < 8; j++)
        #pragma unroll
        for (int l = 0; l < 4; l++) c[j][l] = 0.f;

    // Per-thread A-load source rows (2 float4 loads per k-step)
    const float* arow[2];
    int ak4[2];
    #pragma unroll
    for (int it = 0; it < 2; it++) {
        int idx = tid + it * 256;       // 0..511
        int ml  = idx >> 2;             // 0..127
        ak4[it] = idx & 3;
        int row = m0 + ml;
        int b   = row / R;
        int r   = row % R;
        arow[it] = (r < P) ? (pkg + ((size_t)b * P + r) * D)
                           : (fun + ((size_t)b * F + (r - P)) * D);
    }
    const int bn  = tid >> 2;           // 0..63
    const int bk4 = tid & 3;
    const float* brow = W + (size_t)(n0 + bn) * D;

    for (int k0 = 0; k0 < D; k0 += BK) {
        #pragma unroll
        for (int it = 0; it < 2; it++) {
            int idx = tid + it * 256;
            int ml  = idx >> 2;
            float4 v = *(const float4*)(arow[it] + k0 + ak4[it] * 4);
            As[ak4[it]*4 + 0][ml] = v.x;
            As[ak4[it]*4 + 1][ml] = v.y;
            As[ak4[it]*4 + 2][ml] = v.z;
            As[ak4[it]*4 + 3][ml] = v.w;
        }
        {
            float4 v = *(const float4*)(brow + k0 + bk4 * 4);
            Bs[bk4*4 + 0][bn] = v.x;
            Bs[bk4*4 + 1][bn] = v.y;
            Bs[bk4*4 + 2][bn] = v.z;
            Bs[bk4*4 + 3][bn] = v.w;
        }
        __syncthreads();
        #pragma unroll
        for (int k = 0; k < BK; k++) {
            float a[8], bb[4];
            #pragma unroll
            for (int j = 0; j < 8; j++) a[j] = As[k][ty * 8 + j];
            #pragma unroll
            for (int l = 0; l < 4; l++) bb[l] = Bs[k][tx * 4 + l];
            #pragma unroll
            for (int j = 0; j < 8; j++)
                #pragma unroll
                for (int l = 0; l < 4; l++)
                    c[j][l] += a[j] * bb[l];
        }
        __syncthreads();
    }

    const int col = n0 + tx * 4;
    float4 hb4 = *(const float4*)(hb + col);
    #pragma unroll
    for (int j = 0; j < 8; j++) {
        int row = m0 + ty * 8 + j;
        float4 o;
        o.x = c[j][0] + hb4.x;
        o.y = c[j][1] + hb4.y;
        o.z = c[j][2] + hb4.z;
        o.w = c[j][3] + hb4.w;
        *(float4*)(g_Y + (size_t)row * D + col) = o;
    }
}

// ---------------------------------------------------------------------------
// Kernel B: per-batch tree evaluation + fusion. grid=B, block=256.
// ---------------------------------------------------------------------------
__device__ __forceinline__ float warp_sum(float v) {
    #pragma unroll
    for (int o = 16; o > 0; o >>= 1) v += __shfl_xor_sync(0xffffffffu, v, o);
    return v;
}

// han over n vectors (smem pointers in ptrs): att_j = tanh(v_j) . q ;
// softmax over j ; out[k] = sum_j score_j * v_j[k]. Block-collective.
__device__ void block_han(float* const* ptrs, int n, const float* q,
                          float* att, float* out,
                          int tid, int lane, int wid, int nwarp, int NT) {
    for (int j = wid; j < n; j += nwarp) {
        const float* v = ptrs[j];
        float s = 0.f;
        for (int k = lane; k < D; k += 32) s += tanhf(v[k]) * q[k];
        s = warp_sum(s);
        if (lane == 0) att[j] = s;
    }
    __syncthreads();
    if (tid == 0) {
        float mx = -1e30f;
        for (int j = 0; j < n; j++) mx = fmaxf(mx, att[j]);
        float ssum = 0.f;
        for (int j = 0; j < n; j++) { float e = expf(att[j] - mx); att[j] = e; ssum += e; }
        float inv = 1.f / ssum;
        for (int j = 0; j < n; j++) att[j] *= inv;
    }
    __syncthreads();
    for (int k = tid; k < D; k += NT) {
        float acc = 0.f;
        for (int j = 0; j < n; j++) acc += att[j] * ptrs[j][k];
        out[k] = acc;   // safe in-place: each thread reads its own k before writing
    }
    __syncthreads();
}

__global__ void tree_kernel(const float* __restrict__ nl,
                            const int* __restrict__ levels,
                            const float* __restrict__ fu_w,
                            const float* __restrict__ fu_b,
                            float* __restrict__ out) {
    extern __shared__ float sm[];
    float* q      = sm;                      // D
    float* Ys     = sm + D;                  // R*D
    float* tmp    = Ys + (size_t)R * D;      // D
    float* rootv  = tmp + D;                 // D
    float* att    = rootv + D;               // 64
    int*   parent = (int*)(att + 64);        // 32
    int*   nchild = parent + 32;             // 32
    int*   ncur   = nchild + 32;             // 1 (+1 pad keeps 8B alignment)
    float** ptrs  = (float**)(ncur + 2);     // 44 pointers

    const int b    = blockIdx.x;
    const int tid  = threadIdx.x;
    const int lane = tid & 31;
    const int wid  = tid >> 5;
    const int NT   = blockDim.x;
    const int nwarp = NT >> 5;

    // Load query (nl_vec row) and all 44 transformed vectors to smem
    for (int k = tid; k < D; k += NT) q[k] = nl[(size_t)b * D + k];
    {
        const float4* src = (const float4*)(g_Y + (size_t)b * R * D);
        float4* dst = (float4*)Ys;
        for (int k = tid; k < (R * D) / 4; k += NT) dst[k] = src[k];
    }

    // Parse levels -> parent[] (-2 skipped, -1 root child, else function idx)
    if (tid == 0) {
        for (int i = 0; i < F; i++) { parent[i] = -2; nchild[i] = 0; }
        int curNode = -1, curLevel = -1;
        for (int i = 0; i < F; i++) {
            int l = levels[b * F + i];
            if (l == -1) break;
            if (l - curLevel == 1)      { parent[i] = curNode; curNode = i; curLevel = l; }
            else if (l == curLevel)     { parent[i] = parent[curNode]; curNode = i; }
            else if (l < curLevel) {
                int p = parent[curNode];
                for (int t = 0; t < curLevel - l; t++) p = parent[p];
                parent[i] = p; curNode = i; curLevel = l;
            }
            // else (jump >= +2): node skipped, state unchanged
        }
        for (int i = 0; i < F; i++) if (parent[i] >= 0) nchild[parent[i]]++;
    }
    __syncthreads();

    // Post-order: children have strictly larger indices -> descending sweep
    for (int i = F - 1; i >= 0; i--) {
        if (parent[i] == -2 || nchild[i] == 0) continue;
        if (tid == 0) {
            int n = 0;
            for (int j = i + 1; j < F; j++)
                if (parent[j] == i) ptrs[n++] = Ys + (size_t)(P + j) * D;
            *ncur = n;
        }
        __syncthreads();
        block_han(ptrs, *ncur, q, att, tmp, tid, lane, wid, nwarp, NT);
        if (tid == 0) { ptrs[0] = Ys + (size_t)(P + i) * D; ptrs[1] = tmp; }
        __syncthreads();
        block_han(ptrs, 2, q, att, Ys + (size_t)(P + i) * D, tid, lane, wid, nwarp, NT);
    }

    // Root: packages first, then level-0 functions, in index order
    if (tid == 0) {
        int n = 0;
        for (int r = 0; r < P; r++) ptrs[n++] = Ys + (size_t)r * D;
        for (int i = 0; i < F; i++)
            if (parent[i] == -1) ptrs[n++] = Ys + (size_t)(P + i) * D;
        *ncur = n;
    }
    __syncthreads();
    block_han(ptrs, *ncur, q, att, rootv, tid, lane, wid, nwarp, NT);

    // Fusion: a = softmax([nl.fu_w+b, ctx.fu_w+b]); out = a0*nl + a1*ctx
    if (wid < 2) {
        const float* v = (wid == 0) ? q : rootv;
        float s = 0.f;
        for (int k = lane; k < D; k += 32) s += v[k] * fu_w[k];
        s = warp_sum(s);
        if (lane == 0) att[wid] = s + fu_b[0];
    }
    __syncthreads();
    if (tid == 0) {
        float mx = fmaxf(att[0], att[1]);
        float e0 = expf(att[0] - mx), e1 = expf(att[1] - mx);
        float inv = 1.f / (e0 + e1);
        att[0] = e0 * inv; att[1] = e1 * inv;
    }
    __syncthreads();
    for (int k = tid; k < D; k += NT)
        out[(size_t)b * D + k] = att[0] * q[k] + att[1] * rootv[k];
}

// ---------------------------------------------------------------------------
// Launch
// ---------------------------------------------------------------------------
extern "C" void kernel_launch(void* const* d_in, const int* in_sizes, int n_in,
                              void* d_out, int out_size) {
    const float* nl  = (const float*)d_in[0];   // nl_vec        [64,768]
    const float* pkg = (const float*)d_in[1];   // package_embs  [64,12,768]
    const float* fun = (const float*)d_in[2];   // function_embs [64,32,768]
    const int*   lev = (const int*)  d_in[3];   // levels        [64,32]
    const float* hw  = (const float*)d_in[4];   // han_w [768,768]
    const float* hb  = (const float*)d_in[5];   // han_b [768]
    const float* fuw = (const float*)d_in[6];   // fu_w [1,768]
    const float* fub = (const float*)d_in[7];   // fu_b [1]
    float* out = (float*)d_out;                 // [64,768]

    dim3 g1(D / BN, M_TOT / BM);   // 12 x 22
    gemm_xwT<<<g1, 256>>>(pkg, fun, hw, hb);

    // shared: (D + R*D + D + D + 64) floats + 66 ints + 44 ptrs
    size_t smem = (size_t)(D + (size_t)R * D + D + D + 64) * sizeof(float)
                + 66 * sizeof(int) + 44 * sizeof(float*);
    cudaFuncSetAttribute(tree_kernel, cudaFuncAttributeMaxDynamicSharedMemorySize,
                         (int)smem);
    tree_kernel<<<B, 256, smem>>>(nl, lev, fuw, fub, out);
}